// round 1
// baseline (speedup 1.0000x reference)
#include <cuda_runtime.h>
#include <math.h>

#define N_NODES  100000
#define N_EDGES  3200000
#define HID      128
#define N_GRAPHS 512
#define N_CLASSES 10
#define BN_EPS   1e-5f

// ---------------- scratch (device globals; no allocations) ----------------
__device__ float g_h[N_NODES * HID];     // layer output h
__device__ float g_z[N_NODES * HID];     // aggregated input z
__device__ int   g_deg[N_NODES];
__device__ int   g_off[N_NODES + 1];
__device__ int   g_cur[N_NODES];
__device__ int   g_csr[N_EDGES];         // src ids grouped by dst
__device__ float g_pool[N_GRAPHS * HID];
__device__ float g_cnt[N_GRAPHS];

// ---------------- CSR build ----------------
__global__ void k_zero() {
    int i = blockIdx.x * blockDim.x + threadIdx.x;
    if (i < N_NODES) g_deg[i] = 0;
    if (i < N_GRAPHS * HID) g_pool[i] = 0.0f;
    if (i < N_GRAPHS) g_cnt[i] = 0.0f;
}

__global__ void k_hist(const int* __restrict__ dst) {
    int e = blockIdx.x * blockDim.x + threadIdx.x;
    if (e < N_EDGES) atomicAdd(&g_deg[dst[e]], 1);
}

// single-block exclusive scan over g_deg -> g_off (and g_cur copy)
__global__ void k_scan() {
    __shared__ int s[1024];
    __shared__ int carry;
    int tid = threadIdx.x;
    if (tid == 0) carry = 0;
    __syncthreads();
    for (int base = 0; base < N_NODES; base += 1024) {
        int i = base + tid;
        int v = (i < N_NODES) ? g_deg[i] : 0;
        s[tid] = v;
        __syncthreads();
        int x = v;
        for (int d = 1; d < 1024; d <<= 1) {
            int t = (tid >= d) ? s[tid - d] : 0;
            __syncthreads();
            x += t;
            s[tid] = x;
            __syncthreads();
        }
        int excl = x - v;
        int c = carry;
        if (i < N_NODES) { g_off[i] = c + excl; g_cur[i] = c + excl; }
        __syncthreads();
        if (tid == 1023) carry = c + x;
        __syncthreads();
    }
    if (tid == 0) g_off[N_NODES] = carry;
}

__global__ void k_scatter(const int* __restrict__ src, const int* __restrict__ dst) {
    int e = blockIdx.x * blockDim.x + threadIdx.x;
    if (e < N_EDGES) {
        int pos = atomicAdd(&g_cur[dst[e]], 1);
        g_csr[pos] = src[e];
    }
}

// ---------------- aggregation: z = (1+eps)*h + sum_{src in N(dst)} h[src] ----------------
__global__ void k_agg(const float* __restrict__ x, int layer, const float* __restrict__ epsp) {
    int node = (blockIdx.x * blockDim.x + threadIdx.x) >> 5;
    int lane = threadIdx.x & 31;
    if (node >= N_NODES) return;
    const float* hin = (layer == 0) ? x : (const float*)g_h;
    const float4* hv = (const float4*)hin;
    int beg = g_off[node], end = g_off[node + 1];
    float4 acc = make_float4(0.f, 0.f, 0.f, 0.f);
    for (int base = beg; base < end; base += 32) {
        int n = min(32, end - base);
        int s = (lane < n) ? g_csr[base + lane] : 0;
        for (int j = 0; j < n; j++) {
            int sj = __shfl_sync(0xffffffffu, s, j);
            float4 v = hv[sj * 32 + lane];
            acc.x += v.x; acc.y += v.y; acc.z += v.z; acc.w += v.w;
        }
    }
    float e = 1.0f + epsp[layer];
    float4 self = hv[node * 32 + lane];
    acc.x += e * self.x; acc.y += e * self.y;
    acc.z += e * self.z; acc.w += e * self.w;
    ((float4*)g_z)[node * 32 + lane] = acc;
}

// ---------------- fused MLP: h = BN(relu(relu(z@W1+b1)@W2+b2)) ----------------
#define SZS 132                       // padded row stride for z tile
#define SMEM_MLP ((HID * SZS + HID * HID) * 4)

__device__ __forceinline__ void mm_tile(const float* __restrict__ sZ,
                                        const float* __restrict__ sW,
                                        int r0, int j0, float acc[8][8]) {
    for (int k = 0; k < HID; k += 2) {
        float2 a[8];
#pragma unroll
        for (int i = 0; i < 8; i++)
            a[i] = *(const float2*)&sZ[(r0 + i) * SZS + k];
        float4 w00 = *(const float4*)&sW[k * HID + j0];
        float4 w01 = *(const float4*)&sW[k * HID + j0 + 4];
        float4 w10 = *(const float4*)&sW[(k + 1) * HID + j0];
        float4 w11 = *(const float4*)&sW[(k + 1) * HID + j0 + 4];
        float b0[8] = {w00.x, w00.y, w00.z, w00.w, w01.x, w01.y, w01.z, w01.w};
        float b1v[8] = {w10.x, w10.y, w10.z, w10.w, w11.x, w11.y, w11.z, w11.w};
#pragma unroll
        for (int i = 0; i < 8; i++) {
#pragma unroll
            for (int j = 0; j < 8; j++) {
                acc[i][j] += a[i].x * b0[j];
                acc[i][j] += a[i].y * b1v[j];
            }
        }
    }
}

__global__ void k_mlp(const float* __restrict__ W1, const float* __restrict__ b1,
                      const float* __restrict__ W2, const float* __restrict__ b2,
                      const float* __restrict__ gamma, const float* __restrict__ beta,
                      const float* __restrict__ mu, const float* __restrict__ var) {
    extern __shared__ float smem[];
    float* sZ = smem;                 // [HID][SZS]
    float* sW = smem + HID * SZS;     // [HID][HID]
    int tid = threadIdx.x;            // 256 threads
    int tx = tid & 15, ty = tid >> 4;
    int r0 = ty * 8, j0 = tx * 8;
    int rowBase = blockIdx.x * 128;

    // load z tile (zero-pad OOB rows)
    for (int i = tid; i < 128 * 32; i += 256) {
        int r = i >> 5;
        int c4 = i & 31;
        int gr = rowBase + r;
        float4 v = (gr < N_NODES) ? ((const float4*)g_z)[gr * 32 + c4]
                                  : make_float4(0.f, 0.f, 0.f, 0.f);
        float* p = &sZ[r * SZS + c4 * 4];
        p[0] = v.x; p[1] = v.y; p[2] = v.z; p[3] = v.w;
    }
    // load W1
    for (int i = tid; i < HID * HID / 4; i += 256)
        ((float4*)sW)[i] = ((const float4*)W1)[i];
    __syncthreads();

    float acc[8][8];
#pragma unroll
    for (int i = 0; i < 8; i++)
#pragma unroll
        for (int j = 0; j < 8; j++) acc[i][j] = 0.f;
    mm_tile(sZ, sW, r0, j0, acc);
    __syncthreads();   // all reads of sZ/sW done

    // mid = relu(acc + b1) -> back into sZ ; reload sW with W2
    {
        float bc[8];
#pragma unroll
        for (int j = 0; j < 8; j++) bc[j] = b1[j0 + j];
#pragma unroll
        for (int i = 0; i < 8; i++) {
            float o[8];
#pragma unroll
            for (int j = 0; j < 8; j++) o[j] = fmaxf(acc[i][j] + bc[j], 0.f);
            *(float4*)&sZ[(r0 + i) * SZS + j0]     = make_float4(o[0], o[1], o[2], o[3]);
            *(float4*)&sZ[(r0 + i) * SZS + j0 + 4] = make_float4(o[4], o[5], o[6], o[7]);
        }
    }
    for (int i = tid; i < HID * HID / 4; i += 256)
        ((float4*)sW)[i] = ((const float4*)W2)[i];
    __syncthreads();

#pragma unroll
    for (int i = 0; i < 8; i++)
#pragma unroll
        for (int j = 0; j < 8; j++) acc[i][j] = 0.f;
    mm_tile(sZ, sW, r0, j0, acc);

    // epilogue: bias2 + relu + batchnorm, store to g_h
    float b2c[8], muc[8], scc[8], bec[8];
#pragma unroll
    for (int j = 0; j < 8; j++) {
        int c = j0 + j;
        b2c[j] = b2[c];
        muc[j] = mu[c];
        scc[j] = gamma[c] * rsqrtf(var[c] + BN_EPS);
        bec[j] = beta[c];
    }
#pragma unroll
    for (int i = 0; i < 8; i++) {
        int gr = rowBase + r0 + i;
        if (gr < N_NODES) {
            float o[8];
#pragma unroll
            for (int j = 0; j < 8; j++) {
                float v = fmaxf(acc[i][j] + b2c[j], 0.f);
                o[j] = (v - muc[j]) * scc[j] + bec[j];
            }
            *(float4*)&g_h[gr * HID + j0]     = make_float4(o[0], o[1], o[2], o[3]);
            *(float4*)&g_h[gr * HID + j0 + 4] = make_float4(o[4], o[5], o[6], o[7]);
        }
    }
}

// ---------------- pooling ----------------
__global__ void k_pool(const int* __restrict__ batch) {
    int idx = blockIdx.x * blockDim.x + threadIdx.x;
    int node = idx >> 5, lane = idx & 31;
    if (node >= N_NODES) return;
    int b = batch[node];
    float4 v = ((const float4*)g_h)[node * 32 + lane];
    float* p = &g_pool[b * HID + lane * 4];
    atomicAdd(p + 0, v.x);
    atomicAdd(p + 1, v.y);
    atomicAdd(p + 2, v.z);
    atomicAdd(p + 3, v.w);
    if (lane == 0) atomicAdd(&g_cnt[b], 1.0f);
}

// ---------------- head: mean, lin1+relu, lin2, log_softmax ----------------
__global__ void k_head(const float* __restrict__ l1w, const float* __restrict__ l1b,
                       const float* __restrict__ l2w, const float* __restrict__ l2b,
                       float* __restrict__ out) {
    __shared__ float p[HID], q[HID], r[N_CLASSES];
    int g = blockIdx.x, tid = threadIdx.x;   // 128 threads
    float cnt = fmaxf(g_cnt[g], 1.0f);
    p[tid] = g_pool[g * HID + tid] / cnt;
    __syncthreads();
    float acc = l1b[tid];
    for (int k = 0; k < HID; k++) acc += p[k] * l1w[k * HID + tid];
    q[tid] = fmaxf(acc, 0.f);
    __syncthreads();
    if (tid < N_CLASSES) {
        float a2 = l2b[tid];
        for (int k = 0; k < HID; k++) a2 += q[k] * l2w[k * N_CLASSES + tid];
        r[tid] = a2;
    }
    __syncthreads();
    if (tid < N_CLASSES) {
        float m = -INFINITY;
        for (int j = 0; j < N_CLASSES; j++) m = fmaxf(m, r[j]);
        float s = 0.f;
        for (int j = 0; j < N_CLASSES; j++) s += expf(r[j] - m);
        out[g * N_CLASSES + tid] = r[tid] - m - logf(s);
    }
}

// ---------------- launch ----------------
extern "C" void kernel_launch(void* const* d_in, const int* in_sizes, int n_in,
                              void* d_out, int out_size) {
    const float* x        = (const float*)d_in[0];
    const int*   eidx     = (const int*)d_in[1];
    const int*   batch    = (const int*)d_in[2];
    const float* W1       = (const float*)d_in[3];
    const float* b1       = (const float*)d_in[4];
    const float* W2       = (const float*)d_in[5];
    const float* b2       = (const float*)d_in[6];
    const float* gamma    = (const float*)d_in[7];
    const float* beta     = (const float*)d_in[8];
    const float* bn_mean  = (const float*)d_in[9];
    const float* bn_var   = (const float*)d_in[10];
    const float* eps      = (const float*)d_in[11];
    const float* lin1_w   = (const float*)d_in[12];
    const float* lin1_b   = (const float*)d_in[13];
    const float* lin2_w   = (const float*)d_in[14];
    const float* lin2_b   = (const float*)d_in[15];
    float* out = (float*)d_out;

    const int* src = eidx;
    const int* dst = eidx + N_EDGES;

    cudaFuncSetAttribute(k_mlp, cudaFuncAttributeMaxDynamicSharedMemorySize, SMEM_MLP);

    k_zero<<<(N_NODES + 255) / 256, 256>>>();
    k_hist<<<(N_EDGES + 255) / 256, 256>>>(dst);
    k_scan<<<1, 1024>>>();
    k_scatter<<<(N_EDGES + 255) / 256, 256>>>(src, dst);

    for (int l = 0; l < 3; l++) {
        k_agg<<<(N_NODES * 32 + 255) / 256, 256>>>(x, l, eps);
        k_mlp<<<(N_NODES + 127) / 128, 256, SMEM_MLP>>>(
            W1 + l * HID * HID, b1 + l * HID,
            W2 + l * HID * HID, b2 + l * HID,
            gamma + l * HID, beta + l * HID,
            bn_mean + l * HID, bn_var + l * HID);
    }

    k_pool<<<(N_NODES * 32 + 255) / 256, 256>>>(batch);
    k_head<<<N_GRAPHS, HID>>>(lin1_w, lin1_b, lin2_w, lin2_b, out);
}